// round 2
// baseline (speedup 1.0000x reference)
#include <cuda_runtime.h>
#include <cstdint>

#define TBM 128
#define TBN 128
#define TBK 32
#define NSTG 24        // 768 / 32
#define LDA 36         // padded smem stride (floats): (lane/4)*36+lane%4 is conflict-free
#define D_DIM 768
#define V_OFF (10240*768)

__device__ __forceinline__ uint32_t tf32_rna(float x){
  uint32_t u; asm("cvt.rna.tf32.f32 %0, %1;" : "=r"(u) : "f"(x));
  return u;
}

__device__ __forceinline__ void mma8(float* c,
    uint32_t a0, uint32_t a1, uint32_t a2, uint32_t a3,
    uint32_t b0, uint32_t b1){
  asm volatile(
    "mma.sync.aligned.m16n8k8.row.col.f32.tf32.tf32.f32 "
    "{%0,%1,%2,%3},{%4,%5,%6,%7},{%8,%9},{%0,%1,%2,%3};\n"
    : "+f"(c[0]), "+f"(c[1]), "+f"(c[2]), "+f"(c[3])
    : "r"(a0), "r"(a1), "r"(a2), "r"(a3), "r"(b0), "r"(b1));
}

__global__ void __launch_bounds__(256)
gemma4_patch_embed(const float* __restrict__ pix,      // (16,3,512,512)
                   const float* __restrict__ wproj,    // (768, 768) [d][f]
                   const float* __restrict__ ptab,     // (2, 10240, 768)
                   const int*   __restrict__ pids,     // (16,1024,2)
                   const int*   __restrict__ padp,     // (16,1024) bool-as-int32
                   float* __restrict__ out)            // (16,1024,768)
{
  __shared__ float As[TBM*LDA];
  __shared__ float Bs[TBN*LDA];
  __shared__ int   sO0[TBM];
  __shared__ int   sO1[TBM];
  __shared__ float sPm[TBM];

  const int t  = threadIdx.x;
  const int m0 = blockIdx.y * TBM;
  const int n0 = blockIdx.x * TBN;

  // Preload per-row position ids / padding into smem
  if (t < TBM) {
    int m = m0 + t;
    int x = pids[2*m];     if (x < 0) x = 0;
    int y = pids[2*m + 1]; if (y < 0) y = 0;
    sO0[t] = x * D_DIM;
    sO1[t] = V_OFF + y * D_DIM;
    sPm[t] = (padp[m] != 0) ? 0.f : 1.f;
  }

  // ---- loader indexing (each thread owns 4 float4 per tile per matrix) ----
  const int kq = t & 7;     // which float4 along K (0..7 -> k offsets 0..28)
  const int lr = t >> 3;    // base row 0..31
  int pixBase[4], wBase[4], stsIdx[4];
  #pragma unroll
  for (int j = 0; j < 4; j++) {
    int row = lr + j*32;
    int m = m0 + row;
    int b  = m >> 10;
    int n  = m & 1023;
    int ph = n >> 5, pw = n & 31;
    // pixel addr = b*3*512*512 + c*512*512 + (ph*16+r)*512 + pw*16 + fc
    pixBase[j] = b*786432 + ph*8192 + pw*16;
    wBase[j]   = (n0 + row) * 768;
    stsIdx[j]  = row * LDA + kq*4;
  }

  const int warp = t >> 5, lane = t & 31;
  const int wm = (warp >> 2) * 64;   // warp row base within block tile
  const int wn = (warp & 3) * 32;    // warp col base
  const int g  = lane >> 2, t4 = lane & 3;

  float acc[4][4][4];
  #pragma unroll
  for (int i = 0; i < 4; i++)
    #pragma unroll
    for (int j = 0; j < 4; j++)
      #pragma unroll
      for (int k = 0; k < 4; k++) acc[i][j][k] = 0.f;

  float4 aReg[4], bReg[4];

  auto loadStage = [&](int s){
    int f  = s*TBK + kq*4;           // feature index (same 4-run for all 4 rows)
    int c  = f >> 8;
    int r  = (f >> 4) & 15;
    int fc = f & 15;
    int coff = c*262144 + r*512 + fc;
    #pragma unroll
    for (int j = 0; j < 4; j++)
      aReg[j] = *reinterpret_cast<const float4*>(pix + pixBase[j] + coff);
    #pragma unroll
    for (int j = 0; j < 4; j++)
      bReg[j] = *reinterpret_cast<const float4*>(wproj + wBase[j] + f);
  };

  loadStage(0);

  for (int s = 0; s < NSTG; s++) {
    // STS: transform (2x-1) + round-to-nearest tf32 for A; rna tf32 for B
    #pragma unroll
    for (int j = 0; j < 4; j++) {
      float4 v = aReg[j];
      uint4 u;
      u.x = tf32_rna(fmaf(2.f, v.x, -1.f));
      u.y = tf32_rna(fmaf(2.f, v.y, -1.f));
      u.z = tf32_rna(fmaf(2.f, v.z, -1.f));
      u.w = tf32_rna(fmaf(2.f, v.w, -1.f));
      *reinterpret_cast<uint4*>(reinterpret_cast<uint32_t*>(As) + stsIdx[j]) = u;
    }
    #pragma unroll
    for (int j = 0; j < 4; j++) {
      float4 v = bReg[j];
      uint4 u;
      u.x = tf32_rna(v.x); u.y = tf32_rna(v.y);
      u.z = tf32_rna(v.z); u.w = tf32_rna(v.w);
      *reinterpret_cast<uint4*>(reinterpret_cast<uint32_t*>(Bs) + stsIdx[j]) = u;
    }
    __syncthreads();

    if (s + 1 < NSTG) loadStage(s + 1);   // overlap next-stage LDG with compute

    const uint32_t* Ab = reinterpret_cast<const uint32_t*>(As) + wm*LDA;
    const uint32_t* Bb = reinterpret_cast<const uint32_t*>(Bs) + wn*LDA;
    #pragma unroll
    for (int kk = 0; kk < 4; kk++) {
      uint32_t af[4][4], bf[4][2];
      #pragma unroll
      for (int tm = 0; tm < 4; tm++) {
        const uint32_t* p = Ab + (tm*16 + g)*LDA + kk*8 + t4;
        af[tm][0] = p[0];
        af[tm][2] = p[4];
        af[tm][1] = p[8*LDA];
        af[tm][3] = p[8*LDA + 4];
      }
      #pragma unroll
      for (int tn = 0; tn < 4; tn++) {
        const uint32_t* q = Bb + (tn*8 + g)*LDA + kk*8 + t4;
        bf[tn][0] = q[0];
        bf[tn][1] = q[4];
      }
      #pragma unroll
      for (int tm = 0; tm < 4; tm++)
        #pragma unroll
        for (int tn = 0; tn < 4; tn++)
          mma8(acc[tm][tn], af[tm][0], af[tm][1], af[tm][2], af[tm][3],
               bf[tn][0], bf[tn][1]);
    }
    __syncthreads();
  }

  // ---- epilogue: add gathered position embeddings, masked by padding ----
  #pragma unroll
  for (int tm = 0; tm < 4; tm++) {
    #pragma unroll
    for (int half = 0; half < 2; half++) {
      int lrow = wm + tm*16 + g + half*8;
      int gm   = m0 + lrow;
      int o0   = sO0[lrow];
      int o1   = sO1[lrow];
      float pm = sPm[lrow];
      float* orow = out + (size_t)gm * D_DIM + n0;
      #pragma unroll
      for (int tn = 0; tn < 4; tn++) {
        int col = wn + tn*8 + t4*2;
        int gc  = n0 + col;
        float2 p0 = *reinterpret_cast<const float2*>(ptab + o0 + gc);
        float2 p1 = *reinterpret_cast<const float2*>(ptab + o1 + gc);
        float2 r;
        r.x = acc[tm][tn][half*2 + 0] + pm * (p0.x + p1.x);
        r.y = acc[tm][tn][half*2 + 1] + pm * (p0.y + p1.y);
        *reinterpret_cast<float2*>(orow + col) = r;
      }
    }
  }
}

extern "C" void kernel_launch(void* const* d_in, const int* in_sizes, int n_in,
                              void* d_out, int out_size) {
  const float* pix  = (const float*)d_in[0];
  const float* w    = (const float*)d_in[1];
  const float* tab  = (const float*)d_in[2];
  const int*   pids = (const int*)d_in[3];
  const int*   padp = (const int*)d_in[4];
  float* out = (float*)d_out;

  dim3 grid(D_DIM / TBN, (16 * 1024) / TBM);  // (6, 128)
  gemma4_patch_embed<<<grid, 256>>>(pix, w, tab, pids, padp, out);
}

// round 5
// speedup vs baseline: 1.0021x; 1.0021x over previous
#include <cuda_runtime.h>
#include <cstdint>

#define D_DIM 768
#define V_OFF (10240*768)
#define TBM 128
#define TBN 128
#define NSTG 24
#define LDA 36                      // padded floats/row: conflict-free frag LDS, 16B-aligned rows
#define STAGE_BYTES (TBM*LDA*4)     // 18432
#define NBUF 3
#define SMEM_TOTAL (2*NBUF*STAGE_BYTES)   // 110592

__device__ float g_B[D_DIM*D_DIM];  // tf32_rna(2*W), row-major (d, f)
__device__ float g_CS[D_DIM];       // colsum of W per d

__device__ __forceinline__ uint32_t tf32_rna(float x){
  uint32_t u; asm("cvt.rna.tf32.f32 %0, %1;" : "=r"(u) : "f"(x));
  return u;
}
__device__ __forceinline__ void mma8(float* c,
    uint32_t a0, uint32_t a1, uint32_t a2, uint32_t a3,
    uint32_t b0, uint32_t b1){
  asm volatile(
    "mma.sync.aligned.m16n8k8.row.col.f32.tf32.tf32.f32 "
    "{%0,%1,%2,%3},{%4,%5,%6,%7},{%8,%9},{%0,%1,%2,%3};\n"
    : "+f"(c[0]), "+f"(c[1]), "+f"(c[2]), "+f"(c[3])
    : "r"(a0), "r"(a1), "r"(a2), "r"(a3), "r"(b0), "r"(b1));
}
__device__ __forceinline__ void cpasync16(uint32_t dst, const void* src){
  asm volatile("cp.async.cg.shared.global [%0], [%1], 16;"
               :: "r"(dst), "l"(src) : "memory");
}
__device__ __forceinline__ uint32_t smem_u32(const void* p){
  uint32_t a;
  asm("{ .reg .u64 t; cvta.to.shared.u64 t, %1; cvt.u32.u64 %0, t; }" : "=r"(a) : "l"(p));
  return a;
}

// ---- prep: g_B = rna(2W) ; g_CS = rowsum(W) ----
__global__ void __launch_bounds__(256) prep_b(const float* __restrict__ w){
  const int d = blockIdx.x, t = threadIdx.x;
  __shared__ float red[256];
  float s = 0.f;
  #pragma unroll
  for (int i = t; i < D_DIM; i += 256) {
    float v = w[d*D_DIM + i];
    s += v;
    g_B[d*D_DIM + i] = __uint_as_float(tf32_rna(2.f * v));
  }
  red[t] = s; __syncthreads();
  for (int k = 128; k > 0; k >>= 1) { if (t < k) red[t] += red[t+k]; __syncthreads(); }
  if (t == 0) g_CS[d] = red[0];
}

// ---- main fused GEMM + pos-embed ----
__global__ void __launch_bounds__(256, 2)
gemma4_patch_embed(const float* __restrict__ pix,      // (16,3,512,512)
                   const float* __restrict__ ptab,     // (2,10240,768)
                   const int*   __restrict__ pids,     // (16,1024,2)
                   const int*   __restrict__ padp,     // (16,1024) bool-as-i32
                   float* __restrict__ out)            // (16,1024,768)
{
  extern __shared__ char smem[];
  const uint32_t sA = smem_u32(smem);
  const uint32_t sB = sA + NBUF*STAGE_BYTES;
  const int t  = threadIdx.x;
  const int m0 = blockIdx.y * TBM;
  const int n0 = blockIdx.x * TBN;

  // ---- producer indexing: thread t handles (rows r0+32j, float4 slot kq) ----
  const int kq = t & 7;
  const int r0 = t >> 3;
  int pixBase[4], wBase[4], dstOff[4];
  #pragma unroll
  for (int j = 0; j < 4; j++) {
    int row = r0 + 32*j;
    int m = m0 + row;
    int b = m >> 10, n = m & 1023;
    int ph = n >> 5, pw = n & 31;
    pixBase[j] = b*786432 + ph*8192 + pw*16;
    wBase[j]   = (n0 + row) * D_DIM;
    dstOff[j]  = row*(LDA*4) + kq*16;        // bytes within a stage buffer
  }

  auto issueStage = [&](int s){
    const int buf = s % NBUF;
    const uint32_t aB = sA + buf*STAGE_BYTES;
    const uint32_t bB = sB + buf*STAGE_BYTES;
    const int f    = s*32 + kq*4;
    const int coff = (f >> 8)*262144 + ((f >> 4) & 15)*512 + (f & 15);
    const float* bsrc = g_B + s*32 + kq*4;
    #pragma unroll
    for (int j = 0; j < 4; j++) {
      cpasync16(aB + dstOff[j], pix + pixBase[j] + coff);
      cpasync16(bB + dstOff[j], bsrc + wBase[j]);
    }
  };

  const int warp = t >> 5, lane = t & 31;
  const int wm = (warp >> 2) * 64;
  const int wn = (warp & 3) * 32;
  const int g  = lane >> 2, t4 = lane & 3;

  float acc[4][4][4];
  #pragma unroll
  for (int i = 0; i < 4; i++)
    #pragma unroll
    for (int j = 0; j < 4; j++)
      #pragma unroll
      for (int k = 0; k < 4; k++) acc[i][j][k] = 0.f;

  issueStage(0); asm volatile("cp.async.commit_group;" ::: "memory");
  issueStage(1); asm volatile("cp.async.commit_group;" ::: "memory");

  for (int s = 0; s < NSTG; s++) {
    asm volatile("cp.async.wait_group 1;" ::: "memory");
    __syncthreads();
    if (s + 2 < NSTG) issueStage(s + 2);
    asm volatile("cp.async.commit_group;" ::: "memory");

    const int buf = s % NBUF;
    const uint32_t* Ab = reinterpret_cast<const uint32_t*>(smem + buf*STAGE_BYTES) + wm*LDA;
    const uint32_t* Bb = reinterpret_cast<const uint32_t*>(smem + (NBUF+buf)*STAGE_BYTES) + wn*LDA;
    #pragma unroll
    for (int kk = 0; kk < 4; kk++) {
      uint32_t af[4][4], bf[4][2];
      #pragma unroll
      for (int tm = 0; tm < 4; tm++) {
        const uint32_t* p = Ab + (tm*16 + g)*LDA + kk*8 + t4;
        af[tm][0] = p[0];
        af[tm][2] = p[4];
        af[tm][1] = p[8*LDA];
        af[tm][3] = p[8*LDA + 4];
      }
      #pragma unroll
      for (int tn = 0; tn < 4; tn++) {
        const uint32_t* q = Bb + (tn*8 + g)*LDA + kk*8 + t4;
        bf[tn][0] = q[0];
        bf[tn][1] = q[4];
      }
      #pragma unroll
      for (int tm = 0; tm < 4; tm++)
        #pragma unroll
        for (int tn = 0; tn < 4; tn++)
          mma8(acc[tm][tn], af[tm][0], af[tm][1], af[tm][2], af[tm][3],
               bf[tn][0], bf[tn][1]);
    }
  }

  // ---- epilogue: out = acc - colsum + mask * (tab0[x] + tab1[y]) ----
  #pragma unroll
  for (int tm = 0; tm < 4; tm++) {
    #pragma unroll
    for (int half = 0; half < 2; half++) {
      const int lrow = wm + tm*16 + g + half*8;
      const int m = m0 + lrow;
      int x = pids[2*m];     if (x < 0) x = 0;
      int y = pids[2*m + 1]; if (y < 0) y = 0;
      const float pm = (padp[m] != 0) ? 0.f : 1.f;
      const float* p0 = ptab + x*D_DIM;
      const float* p1 = ptab + V_OFF + y*D_DIM;
      float* orow = out + (size_t)m * D_DIM + n0;
      #pragma unroll
      for (int tn = 0; tn < 4; tn++) {
        const int col = wn + tn*8 + t4*2;
        const int gc  = n0 + col;
        float2 e0 = *reinterpret_cast<const float2*>(p0 + gc);
        float2 e1 = *reinterpret_cast<const float2*>(p1 + gc);
        float2 cs = *reinterpret_cast<const float2*>(g_CS + gc);
        float2 r;
        r.x = acc[tm][tn][half*2 + 0] - cs.x + pm * (e0.x + e1.x);
        r.y = acc[tm][tn][half*2 + 1] - cs.y + pm * (e0.y + e1.y);
        *reinterpret_cast<float2*>(orow + col) = r;
      }
    }
  }
}

extern "C" void kernel_launch(void* const* d_in, const int* in_sizes, int n_in,
                              void* d_out, int out_size) {
  const float* pix  = (const float*)d_in[0];
  const float* w    = (const float*)d_in[1];
  const float* tab  = (const float*)d_in[2];
  const int*   pids = (const int*)d_in[3];
  const int*   padp = (const int*)d_in[4];
  float* out = (float*)d_out;

  prep_b<<<D_DIM, 256>>>(w);

  static int smemSet = 0;
  if (!smemSet) {
    cudaFuncSetAttribute(gemma4_patch_embed,
                         cudaFuncAttributeMaxDynamicSharedMemorySize, SMEM_TOTAL);
    smemSet = 1;
  }
  dim3 grid(D_DIM / TBN, (16 * 1024) / TBM);   // (6, 128)
  gemma4_patch_embed<<<grid, 256, SMEM_TOTAL>>>(pix, tab, pids, padp, out);
}

// round 6
// speedup vs baseline: 1.3604x; 1.3575x over previous
#include <cuda_runtime.h>
#include <cuda_fp16.h>
#include <cstdint>

#define D_DIM 768
#define V_OFF (10240*768)
#define TBM 128
#define TBN 128
#define NSTG 12                  // K stages of 64
#define ASTG 16384               // 128 rows * 128B
#define BSTG 16384
#define SMEM_TOTAL (2*ASTG + 3*BSTG)   // 81920

__device__ __half g_Bh[D_DIM*D_DIM];   // rna fp16 of W, row-major (d, f)

__device__ __forceinline__ uint32_t smem_u32(const void* p){
  uint32_t a;
  asm("{ .reg .u64 t; cvta.to.shared.u64 t, %1; cvt.u32.u64 %0, t; }" : "=r"(a) : "l"(p));
  return a;
}
__device__ __forceinline__ void mma16(float* c, const uint32_t* a, uint32_t b0, uint32_t b1){
  asm volatile(
    "mma.sync.aligned.m16n8k16.row.col.f32.f16.f16.f32 "
    "{%0,%1,%2,%3},{%4,%5,%6,%7},{%8,%9},{%0,%1,%2,%3};\n"
    : "+f"(c[0]), "+f"(c[1]), "+f"(c[2]), "+f"(c[3])
    : "r"(a[0]), "r"(a[1]), "r"(a[2]), "r"(a[3]), "r"(b0), "r"(b1));
}
__device__ __forceinline__ void ldsm4(uint32_t* r, uint32_t addr){
  asm volatile("ldmatrix.sync.aligned.m8n8.x4.shared.b16 {%0,%1,%2,%3}, [%4];"
    : "=r"(r[0]), "=r"(r[1]), "=r"(r[2]), "=r"(r[3]) : "r"(addr));
}
__device__ __forceinline__ void cpasync16(uint32_t dst, const void* src){
  asm volatile("cp.async.cg.shared.global [%0], [%1], 16;"
               :: "r"(dst), "l"(src) : "memory");
}
__device__ __forceinline__ uint32_t pack2(float x, float y){
  __half2 h = __floats2half2_rn(x, y);          // x -> low, y -> high
  return *reinterpret_cast<uint32_t*>(&h);
}

// ---- prep: g_Bh = rn_f16(W) ----
__global__ void __launch_bounds__(256) prep_b(const float* __restrict__ w){
  int i = blockIdx.x * 256 + threadIdx.x;       // grid covers 768*768
  g_Bh[i] = __float2half_rn(w[i]);
}

// ---- main fused GEMM + pos-embed ----
__global__ void __launch_bounds__(256, 2)
gemma4_patch_embed(const float* __restrict__ pix,      // (16,3,512,512)
                   const float* __restrict__ ptab,     // (2,10240,768)
                   const int*   __restrict__ pids,     // (16,1024,2)
                   const int*   __restrict__ padp,     // (16,1024) bool-as-i32
                   float* __restrict__ out)            // (16,1024,768)
{
  extern __shared__ char smem[];
  const uint32_t sA = smem_u32(smem);             // 2 x ASTG
  const uint32_t sB = sA + 2*ASTG;                // 3 x BSTG
  const int t  = threadIdx.x;
  const int m0 = blockIdx.y * TBM;
  const int n0 = blockIdx.x * TBN;

  // ================= producer setup =================
  // A: thread handles rows rA0, rA0+64; k-chunk kq (16 halfs)
  const int kq  = t & 3;
  const int rA0 = t >> 2;                         // 0..63
  const int rx7 = rA0 & 7;                        // (row&7), same for row+64
  int pixBase[2];
  #pragma unroll
  for (int j = 0; j < 2; j++) {
    int m = m0 + rA0 + 64*j;
    int b = m >> 10, n = m & 1023;
    pixBase[j] = b*786432 + (n >> 5)*8192 + (n & 31)*16;
  }
  // A STS destinations (two 16B units per row)
  uint32_t aSts[2][2];
  #pragma unroll
  for (int j = 0; j < 2; j++)
    #pragma unroll
    for (int u = 0; u < 2; u++)
      aSts[j][u] = sA + (rA0 + 64*j)*128 + (((kq*2 + u) ^ rx7) << 4);

  // B: thread handles row rB (d), 4 units
  const int rB  = t >> 1;
  const int ubB = (t & 1) * 4;
  const __half* bSrc0 = g_Bh + (n0 + rB)*D_DIM + ubB*8;
  uint32_t bDst[4];
  #pragma unroll
  for (int u = 0; u < 4; u++)
    bDst[u] = sB + rB*128 + (((ubB + u) ^ (rB & 7)) << 4);

  // ================= consumer setup =================
  const int warp = t >> 5, lid = t & 31;
  const int wm = (warp >> 2) * 64;
  const int wn = (warp & 3) * 32;
  const int h16 = lid >> 4;            // which k-half this lane's ldmatrix ptr serves
  const int x7  = lid & 7;
  uint32_t aLM[4], bLM[2];
  #pragma unroll
  for (int tr = 0; tr < 4; tr++)
    aLM[tr] = sA + (wm + tr*16 + (lid & 15))*128;
  #pragma unroll
  for (int ng = 0; ng < 2; ng++)
    bLM[ng] = sB + (wn + ng*16 + (lid & 15))*128;

  float acc[4][4][4];
  #pragma unroll
  for (int i = 0; i < 4; i++)
    #pragma unroll
    for (int j = 0; j < 4; j++)
      #pragma unroll
      for (int k = 0; k < 4; k++) acc[i][j][k] = 0.f;

  uint4 aH[2][2];   // staged+converted A (2 rows x 2 units)
  auto ldStageA = [&](int s){
    const int f0 = s*64 + kq*16;
    const int off = (f0 >> 8)*262144 + ((f0 >> 4) & 15)*512;
    #pragma unroll
    for (int j = 0; j < 2; j++) {
      const float* p = pix + pixBase[j] + off;
      float4 v0 = *reinterpret_cast<const float4*>(p);
      float4 v1 = *reinterpret_cast<const float4*>(p + 4);
      float4 v2 = *reinterpret_cast<const float4*>(p + 8);
      float4 v3 = *reinterpret_cast<const float4*>(p + 12);
      aH[j][0].x = pack2(fmaf(2.f,v0.x,-1.f), fmaf(2.f,v0.y,-1.f));
      aH[j][0].y = pack2(fmaf(2.f,v0.z,-1.f), fmaf(2.f,v0.w,-1.f));
      aH[j][0].z = pack2(fmaf(2.f,v1.x,-1.f), fmaf(2.f,v1.y,-1.f));
      aH[j][0].w = pack2(fmaf(2.f,v1.z,-1.f), fmaf(2.f,v1.w,-1.f));
      aH[j][1].x = pack2(fmaf(2.f,v2.x,-1.f), fmaf(2.f,v2.y,-1.f));
      aH[j][1].y = pack2(fmaf(2.f,v2.z,-1.f), fmaf(2.f,v2.w,-1.f));
      aH[j][1].z = pack2(fmaf(2.f,v3.x,-1.f), fmaf(2.f,v3.y,-1.f));
      aH[j][1].w = pack2(fmaf(2.f,v3.z,-1.f), fmaf(2.f,v3.w,-1.f));
    }
  };
  auto cpStageB = [&](int s){
    const int buf = (s % 3) * BSTG;
    const __half* src = bSrc0 + s*64;
    #pragma unroll
    for (int u = 0; u < 4; u++)
      cpasync16(bDst[u] + buf, src + u*8);
  };

  // prologue
  ldStageA(0);
  cpStageB(0); asm volatile("cp.async.commit_group;" ::: "memory");
  cpStageB(1); asm volatile("cp.async.commit_group;" ::: "memory");

  for (int s = 0; s < NSTG; s++) {
    // STS A(s) into buf s&1
    {
      const int ab = (s & 1) * ASTG - sA;  // relative adjust trick not needed; compute directly
      #pragma unroll
      for (int j = 0; j < 2; j++)
        #pragma unroll
        for (int u = 0; u < 2; u++)
          *reinterpret_cast<uint4*>((char*)smem + (aSts[j][u] - sA) + (s & 1)*ASTG) = aH[j][u];
      (void)ab;
    }
    asm volatile("cp.async.wait_group 1;" ::: "memory");
    __syncthreads();

    if (s + 1 < NSTG) ldStageA(s + 1);
    if (s + 2 < NSTG) cpStageB(s + 2);
    asm volatile("cp.async.commit_group;" ::: "memory");

    const uint32_t aBuf = (s & 1) * ASTG;
    const uint32_t bBuf = (s % 3) * BSTG;
    #pragma unroll
    for (int kk = 0; kk < 4; kk++) {
      const uint32_t cu16 = (uint32_t)(((kk*2 + h16) ^ x7) << 4);
      uint32_t af[4][4], br[2][4];
      #pragma unroll
      for (int tr = 0; tr < 4; tr++) ldsm4(af[tr], aLM[tr] + aBuf + cu16);
      #pragma unroll
      for (int ng = 0; ng < 2; ng++) ldsm4(br[ng], bLM[ng] + bBuf + cu16);
      #pragma unroll
      for (int tm = 0; tm < 4; tm++) {
        mma16(acc[tm][0], af[tm], br[0][0], br[0][2]);
        mma16(acc[tm][1], af[tm], br[0][1], br[0][3]);
        mma16(acc[tm][2], af[tm], br[1][0], br[1][2]);
        mma16(acc[tm][3], af[tm], br[1][1], br[1][3]);
      }
    }
  }

  // ---- epilogue: add gathered position embeddings, masked by padding ----
  const int g  = lid >> 2, t4 = lid & 3;
  #pragma unroll
  for (int tm = 0; tm < 4; tm++) {
    #pragma unroll
    for (int half = 0; half < 2; half++) {
      const int lrow = wm + tm*16 + g + half*8;
      const int m = m0 + lrow;
      int x = pids[2*m];     if (x < 0) x = 0;
      int y = pids[2*m + 1]; if (y < 0) y = 0;
      const float pm = (padp[m] != 0) ? 0.f : 1.f;
      const float* p0 = ptab + x*D_DIM;
      const float* p1 = ptab + V_OFF + y*D_DIM;
      float* orow = out + (size_t)m * D_DIM + n0;
      #pragma unroll
      for (int tn = 0; tn < 4; tn++) {
        const int col = wn + tn*8 + t4*2;
        const int gc  = n0 + col;
        float2 e0 = *reinterpret_cast<const float2*>(p0 + gc);
        float2 e1 = *reinterpret_cast<const float2*>(p1 + gc);
        float2 r;
        r.x = acc[tm][tn][half*2 + 0] + pm * (e0.x + e1.x);
        r.y = acc[tm][tn][half*2 + 1] + pm * (e0.y + e1.y);
        *reinterpret_cast<float2*>(orow + col) = r;
      }
    }
  }
}

extern "C" void kernel_launch(void* const* d_in, const int* in_sizes, int n_in,
                              void* d_out, int out_size) {
  const float* pix  = (const float*)d_in[0];
  const float* w    = (const float*)d_in[1];
  const float* tab  = (const float*)d_in[2];
  const int*   pids = (const int*)d_in[3];
  const int*   padp = (const int*)d_in[4];
  float* out = (float*)d_out;

  prep_b<<<(D_DIM*D_DIM)/256, 256>>>(w);

  static int smemSet = 0;
  if (!smemSet) {
    cudaFuncSetAttribute(gemma4_patch_embed,
                         cudaFuncAttributeMaxDynamicSharedMemorySize, SMEM_TOTAL);
    smemSet = 1;
  }
  dim3 grid(D_DIM / TBN, (16 * 1024) / TBM);   // (6, 128)
  gemma4_patch_embed<<<grid, 256, SMEM_TOTAL>>>(pix, tab, pids, padp, out);
}